// round 14
// baseline (speedup 1.0000x reference)
#include <cuda_runtime.h>
#include <cuda_bf16.h>
#include <cstdint>

#define FULLMASK 0xffffffffu
typedef unsigned long long u64;

// Scratch (static device globals; no allocation allowed)
__device__ float4 g_z[256 * 1024];          // [B][T_out] latent trajectory
__device__ float  g_xw[256 * 512 * 60];     // [B][T_in(flipped)][3*RHID]
__device__ int    g_flag[1024];             // per-(b,tile) ready flags

// ---------------------------------------------------------------------------
// math helpers
// ---------------------------------------------------------------------------
__device__ __forceinline__ float sigm(float x) {
    return __fdividef(1.f, 1.f + __expf(-x));
}
__device__ __forceinline__ float tanhfast(float x) {
    x = fmaxf(x, -15.f);
    float e = __expf(-2.f * x);
    return __fdividef(1.f - e, 1.f + e);
}
__device__ __forceinline__ float eluf(float x) {
    float e = __expf(x) - 1.f;
    return x > 0.f ? x : e;
}
__device__ __forceinline__ float sel4(const float (&a)[4], int i) {
    float r = a[0];
    r = (i == 1) ? a[1] : r;
    r = (i == 2) ? a[2] : r;
    r = (i == 3) ? a[3] : r;
    return r;
}
__device__ __forceinline__ unsigned smem_u32(const void* p) {
    unsigned a;
    asm("{ .reg .u64 t; cvta.to.shared.u64 t, %1; cvt.u32.u64 %0, t; }"
        : "=r"(a) : "l"(p));
    return a;
}
#define CP_ASYNC16(dst, src) \
    asm volatile("cp.async.ca.shared.global [%0], [%1], 16;" :: "r"(dst), "l"(src))
#define CP_COMMIT() asm volatile("cp.async.commit_group;")
#define CP_WAIT1()  asm volatile("cp.async.wait_group 1;")
#define CP_WAIT0()  asm volatile("cp.async.wait_group 0;")

// ---- packed f32x2 helpers (bitwise-identical to 2 independent fp32 ops) ----
__device__ __forceinline__ u64 pack2(float lo, float hi) {
    u64 r; asm("mov.b64 %0, {%1, %2};" : "=l"(r) : "f"(lo), "f"(hi)); return r;
}
__device__ __forceinline__ void unpack2(u64 v, float& lo, float& hi) {
    asm("mov.b64 {%0, %1}, %2;" : "=f"(lo), "=f"(hi) : "l"(v));
}
__device__ __forceinline__ u64 fma2(u64 a, u64 b, u64 c) {
    u64 r; asm("fma.rn.f32x2 %0, %1, %2, %3;" : "=l"(r) : "l"(a), "l"(b), "l"(c));
    return r;
}
__device__ __forceinline__ u64 add2(u64 a, u64 b) {
    u64 r; asm("add.rn.f32x2 %0, %1, %2;" : "=l"(r) : "l"(a), "l"(b)); return r;
}
__device__ __forceinline__ float hadd2(u64 v) {
    float lo, hi; unpack2(v, lo, hi); return lo + hi;
}

// dot of per-lane weight row w[20] with a 20-vector distributed one-per-lane
__device__ __forceinline__ float dot20b(const float (&w)[20], float v, float init) {
    float s0 = init, s1 = 0.f, s2 = 0.f, s3 = 0.f;
#pragma unroll
    for (int k = 0; k < 20; k += 4) {
        float v0 = __shfl_sync(FULLMASK, v, k);
        float v1 = __shfl_sync(FULLMASK, v, k + 1);
        float v2 = __shfl_sync(FULLMASK, v, k + 2);
        float v3 = __shfl_sync(FULLMASK, v, k + 3);
        s0 = fmaf(w[k],     v0, s0);
        s1 = fmaf(w[k + 1], v1, s1);
        s2 = fmaf(w[k + 2], v2, s2);
        s3 = fmaf(w[k + 3], v3, s3);
    }
    return (s0 + s1) + (s2 + s3);
}

// ---------------------------------------------------------------------------
// ODE helpers (merged-stage algebra: M = W_f1*W_f5, beta = W_f1*b5)
// ---------------------------------------------------------------------------
struct OdeW {
    float wf1[4], wf2[20], wf3[20], wf4[20], M[20], wf5r[20];
    float b1, b2, b3, b4, b5r, beta;
};

__device__ __forceinline__ float stage_m(const OdeW& W, float hp, float c, float A) {
    float t  = fmaf(c, dot20b(W.M, hp, W.beta), A);
    float h1 = eluf(t);
    float h2 = eluf(dot20b(W.wf2, h1, W.b2));
    float h3 = eluf(dot20b(W.wf3, h2, W.b3));
    return     eluf(dot20b(W.wf4, h3, W.b4));
}

__device__ __forceinline__ float stage_1(const OdeW& W, const float (&z)[4], float& Aout) {
    float A = W.b1;
#pragma unroll
    for (int i = 0; i < 4; ++i) A = fmaf(W.wf1[i], z[i], A);
    Aout = A;
    float h1 = eluf(A);
    float h2 = eluf(dot20b(W.wf2, h1, W.b2));
    float h3 = eluf(dot20b(W.wf3, h2, W.b3));
    return     eluf(dot20b(W.wf4, h3, W.b4));
}

// ---------------------------------------------------------------------------
// flag clear kernel (graph-replay determinism)
// ---------------------------------------------------------------------------
__global__ void clear_kernel() {
    g_flag[blockIdx.x * 256 + threadIdx.x] = 0;
}

// ---------------------------------------------------------------------------
// Fused kernel:
//   blocks 0..63      : scan path (4 warps = 4 batch elems each)
//   blocks 64..1087   : xw producer blocks (R11 design), tile-major order,
//                       signal g_flag[b*4+tile] on completion.
// Dynamic smem 51200 B (xw: Xs[64][132]+Ws[64][68]; scan: 4 x 2 x 960 floats).
// ---------------------------------------------------------------------------
#define FUSED_SMEM_BYTES 51200

__global__ void __launch_bounds__(128, 4) fused_kernel(
    const float* __restrict__ x,
    const float* __restrict__ W_ih, const float* __restrict__ b_ih,
    const float* __restrict__ W_hh, const float* __restrict__ b_hh,
    const float* __restrict__ W_rl, const float* __restrict__ b_rl,
    const float* __restrict__ W_f1, const float* __restrict__ b_f1,
    const float* __restrict__ W_f2, const float* __restrict__ b_f2,
    const float* __restrict__ W_f3, const float* __restrict__ b_f3,
    const float* __restrict__ W_f4, const float* __restrict__ b_f4,
    const float* __restrict__ W_f5, const float* __restrict__ b_f5)
{
    extern __shared__ float sm[];

    if (blockIdx.x >= 64) {
        // ================= xw producer path (R11 design, proven 108us) ======
        float* Xs = sm;               // [64][132]
        float* Ws = sm + 64 * 132;    // [64][68]

        const int xwid = blockIdx.x - 64;
        const int tile = xwid >> 8;   // 0..3 (tile-major: all b of tile0 first)
        const int b    = xwid & 255;
        const int t0   = tile * 128;
        const int tid  = threadIdx.x;
        const int sgi  = tid & 15;    // ts-octet (ts = 8*sgi..+7)
        const int ggi  = tid >> 4;    // gate-octet (g = 8*ggi..+7)

        u64 acc[4][8] = {};           // [ts-pair][gate] packed f32x2

        for (int c = 0; c < 3; ++c) {
            {   // stage X chunk: thread owns ts-row tid, 64 k values
                const float4* src = (const float4*)(
                    x + (((size_t)b * 3 + c) * 512 + (511 - (t0 + tid))) * 64);
#pragma unroll
                for (int v = 0; v < 16; ++v) {
                    float4 val = src[v];
                    Xs[(4 * v + 0) * 132 + tid] = val.x;
                    Xs[(4 * v + 1) * 132 + tid] = val.y;
                    Xs[(4 * v + 2) * 132 + tid] = val.z;
                    Xs[(4 * v + 3) * 132 + tid] = val.w;
                }
            }
            for (int i = tid; i < 64 * 64; i += 128) {
                int g = i >> 6, kk = i & 63;
                Ws[kk * 68 + g] = (g < 60) ? W_ih[g * 192 + c * 64 + kk] : 0.f;
            }
            __syncthreads();

#pragma unroll 2
            for (int kk = 0; kk < 64; ++kk) {
                const float* xr = Xs + kk * 132 + 8 * sgi;
                const float* wr = Ws + kk * 68  + 8 * ggi;
                ulonglong2 xA = *(const ulonglong2*)xr;
                ulonglong2 xB = *(const ulonglong2*)(xr + 4);
                float4 wa = *(const float4*)wr;
                float4 wb = *(const float4*)(wr + 4);
                u64 xp[4] = { xA.x, xA.y, xB.x, xB.y };
                u64 wp[8];
                wp[0] = pack2(wa.x, wa.x); wp[1] = pack2(wa.y, wa.y);
                wp[2] = pack2(wa.z, wa.z); wp[3] = pack2(wa.w, wa.w);
                wp[4] = pack2(wb.x, wb.x); wp[5] = pack2(wb.y, wb.y);
                wp[6] = pack2(wb.z, wb.z); wp[7] = pack2(wb.w, wb.w);
#pragma unroll
                for (int i2 = 0; i2 < 4; ++i2)
#pragma unroll
                    for (int m = 0; m < 8; ++m)
                        acc[i2][m] = fma2(xp[i2], wp[m], acc[i2][m]);
            }
            __syncthreads();
        }

        float gb[8];
#pragma unroll
        for (int m = 0; m < 8; ++m) {
            int g = 8 * ggi + m;
            gb[m] = (g < 60) ? b_ih[g] : 0.f;
        }
#pragma unroll
        for (int i2 = 0; i2 < 4; ++i2) {
            float r0[8], r1[8];
#pragma unroll
            for (int m = 0; m < 8; ++m) {
                unpack2(acc[i2][m], r0[m], r1[m]);
                r0[m] += gb[m]; r1[m] += gb[m];
            }
            size_t row0 = (size_t)b * 512 + t0 + 8 * sgi + 2 * i2;
            float* d0 = g_xw + row0 * 60 + 8 * ggi;
            float* d1 = d0 + 60;
            *(float4*)d0 = make_float4(r0[0], r0[1], r0[2], r0[3]);
            *(float4*)d1 = make_float4(r1[0], r1[1], r1[2], r1[3]);
            if (ggi < 7) {
                *(float4*)(d0 + 4) = make_float4(r0[4], r0[5], r0[6], r0[7]);
                *(float4*)(d1 + 4) = make_float4(r1[4], r1[5], r1[6], r1[7]);
            }
        }

        // signal tile ready (release: bar + fence + atomic)
        __syncthreads();
        if (tid == 0) {
            __threadfence();
            atomicExch(&g_flag[b * 4 + tile], 1);
        }
        return;
    }

    // ================= scan path: 4 warps = 4 batch elems ===================
    const int wid  = threadIdx.x >> 5;
    const int lane = threadIdx.x & 31;
    const int b    = blockIdx.x * 4 + wid;
    const int j    = (lane < 20) ? lane : 0;
    const int j4   = (lane < 4)  ? lane : 0;
    float* xs = sm + wid * 2 * 960;        // per-warp double buffer (16 steps)

    // ---- GRU weights, packed in k-pairs ----
    u64 whrp[10], whzp[10], whnp[10], hp[10];
#pragma unroll
    for (int k = 0; k < 10; ++k) {
        whrp[k] = pack2(W_hh[j * 20 + 2 * k],        W_hh[j * 20 + 2 * k + 1]);
        whzp[k] = pack2(W_hh[(20 + j) * 20 + 2 * k], W_hh[(20 + j) * 20 + 2 * k + 1]);
        whnp[k] = pack2(W_hh[(40 + j) * 20 + 2 * k], W_hh[(40 + j) * 20 + 2 * k + 1]);
        hp[k]   = pack2(0.f, 0.f);
    }
    const float bhr = b_hh[j], bhz = b_hh[20 + j], bhn = b_hh[40 + j];
    const u64 zero2 = pack2(0.f, 0.f);
    float hself = 0.f;

    const float* xwb = g_xw + (size_t)b * 512 * 60;

    // tile-ready wait (acquire: spin + fence)
    auto wait_tile = [&](int tl) {
        if (lane == 0) {
            while (atomicAdd(&g_flag[b * 4 + tl], 0) == 0) __nanosleep(128);
        }
        __syncwarp();
        __threadfence();
    };
    // prefetch 16-step chunk k into buffer buf
    auto prefetch = [&](int k, int buf) {
        const float4* src = (const float4*)(xwb + (size_t)k * 960);
        unsigned dst = smem_u32(xs + buf * 960);
#pragma unroll
        for (int r = 0; r < 8; ++r) {
            int i = lane + 32 * r;
            if (i < 240) CP_ASYNC16(dst + (unsigned)i * 16u, src + i);
        }
        CP_COMMIT();
    };

    wait_tile(0);
    prefetch(0, 0);

    for (int c = 0; c < 32; ++c) {
        if (c < 31) {
            if (((c + 1) & 7) == 0) wait_tile((c + 1) >> 3);
            prefetch(c + 1, (c + 1) & 1);
            CP_WAIT1();
        } else {
            CP_WAIT0();
        }
        __syncwarp();

        const float* X = xs + (c & 1) * 960;
        float xr = X[j], xz = X[20 + j], xn = X[40 + j];
        for (int s2 = 0; s2 < 16; ++s2) {
            int sn = (s2 < 15) ? s2 + 1 : s2;
            float nxr = X[sn * 60 + j];
            float nxz = X[sn * 60 + 20 + j];
            float nxn = X[sn * 60 + 40 + j];

            u64 r0 = pack2(bhr, 0.f), r1 = zero2;
            u64 q0 = pack2(bhz, 0.f), q1 = zero2;
            u64 n0 = pack2(bhn, 0.f), n1 = zero2;
#pragma unroll
            for (int kp = 0; kp < 10; kp += 2) {
                r0 = fma2(whrp[kp],     hp[kp],     r0);
                r1 = fma2(whrp[kp + 1], hp[kp + 1], r1);
                q0 = fma2(whzp[kp],     hp[kp],     q0);
                q1 = fma2(whzp[kp + 1], hp[kp + 1], q1);
                n0 = fma2(whnp[kp],     hp[kp],     n0);
                n1 = fma2(whnp[kp + 1], hp[kp + 1], n1);
            }
            float gr = hadd2(add2(r0, r1));
            float gz = hadd2(add2(q0, q1));
            float gn = hadd2(add2(n0, n1));

            float rg   = sigm(xr + gr);
            float zg   = sigm(xz + gz);
            float ng   = tanhfast(xn + rg * gn);
            float hnew = (1.f - zg) * ng + zg * hself;
            hself = hnew;
#pragma unroll
            for (int k = 0; k < 10; ++k) {
                float va = __shfl_sync(FULLMASK, hnew, 2 * k);
                float vb = __shfl_sync(FULLMASK, hnew, 2 * k + 1);
                hp[k] = pack2(va, vb);
            }
            xr = nxr; xz = nxz; xn = nxn;
        }
    }

    // ---- z0 = hT @ W_rl^T + b_rl (packed) ----
    float za;
    {
        u64 s0 = pack2(b_rl[j4], 0.f), s1 = zero2;
#pragma unroll
        for (int k = 0; k < 10; k += 2) {
            s0 = fma2(pack2(W_rl[j4 * 20 + 2 * k],     W_rl[j4 * 20 + 2 * k + 1]), hp[k],     s0);
            s1 = fma2(pack2(W_rl[j4 * 20 + 2 * k + 2], W_rl[j4 * 20 + 2 * k + 3]), hp[k + 1], s1);
        }
        za = hadd2(add2(s0, s1));
    }
    float z[4];
#pragma unroll
    for (int i = 0; i < 4; ++i) z[i] = __shfl_sync(FULLMASK, za, i);

    float4* zb = g_z + (size_t)b * 1024;
    float*  zf = (float*)zb;
    if (lane == 0) zb[0] = make_float4(z[0], z[1], z[2], z[3]);

    // ---- ODE weights ----
    OdeW W;
#pragma unroll
    for (int k = 0; k < 4; ++k) W.wf1[k] = W_f1[j * 4 + k];
#pragma unroll
    for (int k = 0; k < 20; ++k) {
        W.wf2[k]  = W_f2[j * 20 + k];
        W.wf3[k]  = W_f3[j * 20 + k];
        W.wf4[k]  = W_f4[j * 20 + k];
        W.wf5r[k] = W_f5[j4 * 20 + k];
        float m = 0.f;
#pragma unroll
        for (int i = 0; i < 4; ++i) m = fmaf(W.wf1[i], W_f5[i * 20 + k], m);
        W.M[k] = m;
    }
    {
        float bt = 0.f;
#pragma unroll
        for (int i = 0; i < 4; ++i) bt = fmaf(W.wf1[i], b_f5[i], bt);
        W.beta = bt;
    }
    W.b1 = b_f1[j]; W.b2 = b_f2[j]; W.b3 = b_f3[j]; W.b4 = b_f4[j];
    W.b5r = b_f5[j4];

    const float H   = 1.28f;
    const float HD2 = 0.64f;
    const float HD6 = H / 6.0f;
    const int cI = lane & 3;

    float A;
    float h4s1 = stage_1(W, z, A);
    float k1[4];
    {
        float o = dot20b(W.wf5r, h4s1, W.b5r);
#pragma unroll
        for (int i = 0; i < 4; ++i) k1[i] = __shfl_sync(FULLMASK, o, i);
    }

    for (int n = 0; n < 8; ++n) {
        float Hsum = h4s1;
        float h4 = stage_m(W, h4s1, HD2, A);  Hsum = fmaf(2.f, h4, Hsum);
        h4       = stage_m(W, h4,   HD2, A);  Hsum = fmaf(2.f, h4, Hsum);
        h4       = stage_m(W, h4,   H,   A);  Hsum += h4;

        float oS = dot20b(W.wf5r, Hsum, 6.f * W.b5r);
        float zn[4];
#pragma unroll
        for (int i = 0; i < 4; ++i)
            zn[i] = fmaf(HD6, __shfl_sync(FULLMASK, oS, i), z[i]);

        float An;
        float h4n = stage_1(W, zn, An);
        float k1n[4];
        {
            float o1 = dot20b(W.wf5r, h4n, W.b5r);
#pragma unroll
            for (int i = 0; i < 4; ++i) k1n[i] = __shfl_sync(FULLMASK, o1, i);
        }

        float z0c = sel4(z, cI),  z1c = sel4(zn, cI);
        float F0  = H * sel4(k1, cI), F1 = H * sel4(k1n, cI);
#pragma unroll
        for (int r = 0; r < 16; ++r) {
            int vi = lane + 32 * r;
            int p  = vi >> 2;
            int idx = 128 * n + 1 + p;
            if (idx < 1024) {
                float s  = (float)(p + 1) * 0.0078125f;
                float s2 = s * s, om = 1.f - s;
                float h00 = (1.f + 2.f * s) * om * om;
                float h10 = s * om * om;
                float h01 = s2 * (3.f - 2.f * s);
                float h11 = s2 * (s - 1.f);
                zf[idx * 4 + cI] = h00 * z0c + h01 * z1c + h10 * F0 + h11 * F1;
            }
        }

#pragma unroll
        for (int i = 0; i < 4; ++i) { z[i] = zn[i]; k1[i] = k1n[i]; }
        A = An; h4s1 = h4n;
    }
}

// ---------------------------------------------------------------------------
// Kernel 3: decoder. 2 warps per (b, 128-ts tile), 3 gate-rows each.
// ---------------------------------------------------------------------------
__global__ __launch_bounds__(256) void dec_kernel(
    const float* __restrict__ W_d1, const float* __restrict__ b_d1,
    const float* __restrict__ W_d2, const float* __restrict__ b_d2,
    float* __restrict__ out)
{
    const int w    = blockIdx.x * 8 + (threadIdx.x >> 5);   // 0..4095
    const int lane = threadIdx.x & 31;
    const int b    = w >> 4;
    const int rem  = w & 15;
    const int t0   = (rem >> 1) << 7;
    const int half = rem & 1;
    const int j    = (lane < 20) ? lane : 0;

    float wd1[4];
#pragma unroll
    for (int i = 0; i < 4; ++i) wd1[i] = W_d1[j * 4 + i];
    const float bd1v = b_d1[j];

    u64 wd2p[3][10];
    float bd2v[3];
    int gidx[3];
#pragma unroll
    for (int r = 0; r < 3; ++r) {
        int g = lane + 32 * (3 * half + r);
        gidx[r] = g;
#pragma unroll
        for (int k = 0; k < 10; ++k)
            wd2p[r][k] = pack2(W_d2[g * 20 + 2 * k], W_d2[g * 20 + 2 * k + 1]);
        bd2v[r] = b_d2[g];
    }
    const u64 zero2 = pack2(0.f, 0.f);

    const float4* zp = g_z + (size_t)b * 1024 + t0;
    float4 zc = zp[0];
    for (int tt = 0; tt < 128; ++tt) {
        float4 zn = zp[(tt < 127) ? (tt + 1) : tt];
        float t = bd1v;
        t = fmaf(wd1[0], zc.x, t); t = fmaf(wd1[1], zc.y, t);
        t = fmaf(wd1[2], zc.z, t); t = fmaf(wd1[3], zc.w, t);
        float hj = fmaxf(t, 0.f);

        u64 hhp[10];
#pragma unroll
        for (int k = 0; k < 10; ++k) {
            float va = __shfl_sync(FULLMASK, hj, 2 * k);
            float vb = __shfl_sync(FULLMASK, hj, 2 * k + 1);
            hhp[k] = pack2(va, vb);
        }

        const int tg = t0 + tt;
#pragma unroll
        for (int r = 0; r < 3; ++r) {
            u64 s0 = pack2(bd2v[r], 0.f), s1 = zero2;
#pragma unroll
            for (int k = 0; k < 10; k += 2) {
                s0 = fma2(wd2p[r][k],     hhp[k],     s0);
                s1 = fma2(wd2p[r][k + 1], hhp[k + 1], s1);
            }
            float v = hadd2(add2(s0, s1));
            int g = gidx[r];
            int c = g >> 6, f = g & 63;
            out[(((size_t)b * 3 + c) * 1024 + tg) * 64 + f] = v;
        }
        zc = zn;
    }
}

// ---------------------------------------------------------------------------
extern "C" void kernel_launch(void* const* d_in, const int* in_sizes, int n_in,
                              void* d_out, int out_size) {
    const float* x    = (const float*)d_in[0];
    const float* W_ih = (const float*)d_in[2];
    const float* b_ih = (const float*)d_in[3];
    const float* W_hh = (const float*)d_in[4];
    const float* b_hh = (const float*)d_in[5];
    const float* W_rl = (const float*)d_in[6];
    const float* b_rl = (const float*)d_in[7];
    const float* W_f1 = (const float*)d_in[8];
    const float* b_f1 = (const float*)d_in[9];
    const float* W_f2 = (const float*)d_in[10];
    const float* b_f2 = (const float*)d_in[11];
    const float* W_f3 = (const float*)d_in[12];
    const float* b_f3 = (const float*)d_in[13];
    const float* W_f4 = (const float*)d_in[14];
    const float* b_f4 = (const float*)d_in[15];
    const float* W_f5 = (const float*)d_in[16];
    const float* b_f5 = (const float*)d_in[17];
    const float* W_d1 = (const float*)d_in[18];
    const float* b_d1 = (const float*)d_in[19];
    const float* W_d2 = (const float*)d_in[20];
    const float* b_d2 = (const float*)d_in[21];
    float* out = (float*)d_out;

    static bool attr_set = false;
    if (!attr_set) {
        cudaFuncSetAttribute(fused_kernel,
                             cudaFuncAttributeMaxDynamicSharedMemorySize,
                             FUSED_SMEM_BYTES);
        attr_set = true;
    }

    clear_kernel<<<4, 256>>>();
    fused_kernel<<<64 + 1024, 128, FUSED_SMEM_BYTES>>>(
        x, W_ih, b_ih, W_hh, b_hh, W_rl, b_rl,
        W_f1, b_f1, W_f2, b_f2, W_f3, b_f3,
        W_f4, b_f4, W_f5, b_f5);
    dec_kernel<<<512, 256>>>(W_d1, b_d1, W_d2, b_d2, out);
}

// round 15
// speedup vs baseline: 5.8721x; 5.8721x over previous
#include <cuda_runtime.h>
#include <cuda_bf16.h>
#include <cstdint>

#define FULLMASK 0xffffffffu
typedef unsigned long long u64;

// Scratch (static device global; no allocation allowed)
__device__ float4 g_z[256 * 1024];          // [B][T_out] latent trajectory
__device__ float  g_xw[256 * 512 * 60];     // [B][T_in(flipped)][3*RHID]

// ---------------------------------------------------------------------------
// math helpers
// ---------------------------------------------------------------------------
__device__ __forceinline__ float sigm(float x) {
    return __fdividef(1.f, 1.f + __expf(-x));
}
__device__ __forceinline__ float tanhfast(float x) {
    x = fmaxf(x, -15.f);
    float e = __expf(-2.f * x);
    return __fdividef(1.f - e, 1.f + e);
}
__device__ __forceinline__ float eluf(float x) {
    float e = __expf(x) - 1.f;
    return x > 0.f ? x : e;
}
__device__ __forceinline__ float sel4(const float (&a)[4], int i) {
    float r = a[0];
    r = (i == 1) ? a[1] : r;
    r = (i == 2) ? a[2] : r;
    r = (i == 3) ? a[3] : r;
    return r;
}
__device__ __forceinline__ unsigned smem_u32(const void* p) {
    unsigned a;
    asm("{ .reg .u64 t; cvta.to.shared.u64 t, %1; cvt.u32.u64 %0, t; }"
        : "=r"(a) : "l"(p));
    return a;
}
#define CP_ASYNC16(dst, src) \
    asm volatile("cp.async.ca.shared.global [%0], [%1], 16;" :: "r"(dst), "l"(src))
#define CP_COMMIT() asm volatile("cp.async.commit_group;")
#define CP_WAIT1()  asm volatile("cp.async.wait_group 1;")
#define CP_WAIT0()  asm volatile("cp.async.wait_group 0;")

// ---- packed f32x2 helpers (bitwise-identical to 2 independent fp32 ops) ----
__device__ __forceinline__ u64 pack2(float lo, float hi) {
    u64 r; asm("mov.b64 %0, {%1, %2};" : "=l"(r) : "f"(lo), "f"(hi)); return r;
}
__device__ __forceinline__ void unpack2(u64 v, float& lo, float& hi) {
    asm("mov.b64 {%0, %1}, %2;" : "=f"(lo), "=f"(hi) : "l"(v));
}
__device__ __forceinline__ u64 fma2(u64 a, u64 b, u64 c) {
    u64 r; asm("fma.rn.f32x2 %0, %1, %2, %3;" : "=l"(r) : "l"(a), "l"(b), "l"(c));
    return r;
}
__device__ __forceinline__ u64 add2(u64 a, u64 b) {
    u64 r; asm("add.rn.f32x2 %0, %1, %2;" : "=l"(r) : "l"(a), "l"(b)); return r;
}
__device__ __forceinline__ float hadd2(u64 v) {
    float lo, hi; unpack2(v, lo, hi); return lo + hi;
}

// dot of per-lane weight row w[20] with a 20-vector distributed one-per-lane
__device__ __forceinline__ float dot20b(const float (&w)[20], float v, float init) {
    float s0 = init, s1 = 0.f, s2 = 0.f, s3 = 0.f;
#pragma unroll
    for (int k = 0; k < 20; k += 4) {
        float v0 = __shfl_sync(FULLMASK, v, k);
        float v1 = __shfl_sync(FULLMASK, v, k + 1);
        float v2 = __shfl_sync(FULLMASK, v, k + 2);
        float v3 = __shfl_sync(FULLMASK, v, k + 3);
        s0 = fmaf(w[k],     v0, s0);
        s1 = fmaf(w[k + 1], v1, s1);
        s2 = fmaf(w[k + 2], v2, s2);
        s3 = fmaf(w[k + 3], v3, s3);
    }
    return (s0 + s1) + (s2 + s3);
}

// ---------------------------------------------------------------------------
// Kernel 1: xw[b][s][g] = b_ih[g] + sum_k x_flat[b][511-s][k] * W_ih[g][k]
// R11 design (measured 108us): 128ts x 64g(padded) block tile, 128 threads,
// 8ts x 8g per-thread tiles, packed f32x2 FMA. k staged in 3 chunks of 64.
// Transposed smem: Xs[k][ts] stride 132, Ws[k][g] stride 68. smem 51.2 KB.
// ---------------------------------------------------------------------------
__global__ void __launch_bounds__(128) xw_kernel(
    const float* __restrict__ x, const float* __restrict__ W_ih,
    const float* __restrict__ b_ih)
{
    extern __shared__ float sm[];
    float* Xs = sm;               // [64][132]
    float* Ws = sm + 64 * 132;    // [64][68]

    const int b   = blockIdx.y;
    const int t0  = blockIdx.x * 128;
    const int tid = threadIdx.x;
    const int sgi = tid & 15;     // ts-octet index (ts = 8*sgi .. +7)
    const int ggi = tid >> 4;     // gate-octet index (g = 8*ggi .. +7)

    u64 acc[4][8] = {};           // [ts-pair][gate] packed f32x2

    for (int c = 0; c < 3; ++c) {
        // --- stage X chunk: thread owns ts-row `tid`, reads 64 k values
        {
            const float4* src = (const float4*)(
                x + (((size_t)b * 3 + c) * 512 + (511 - (t0 + tid))) * 64);
#pragma unroll
            for (int v = 0; v < 16; ++v) {
                float4 val = src[v];
                Xs[(4 * v + 0) * 132 + tid] = val.x;
                Xs[(4 * v + 1) * 132 + tid] = val.y;
                Xs[(4 * v + 2) * 132 + tid] = val.z;
                Xs[(4 * v + 3) * 132 + tid] = val.w;
            }
        }
        // --- stage W chunk (gates padded 60 -> 64 with zeros)
        for (int i = tid; i < 64 * 64; i += 128) {
            int g = i >> 6, kk = i & 63;
            Ws[kk * 68 + g] = (g < 60) ? W_ih[g * 192 + c * 64 + kk] : 0.f;
        }
        __syncthreads();

#pragma unroll 2
        for (int kk = 0; kk < 64; ++kk) {
            const float* xr = Xs + kk * 132 + 8 * sgi;
            const float* wr = Ws + kk * 68  + 8 * ggi;
            ulonglong2 xA = *(const ulonglong2*)xr;          // ts pairs 0,1
            ulonglong2 xB = *(const ulonglong2*)(xr + 4);    // ts pairs 2,3
            float4 wa = *(const float4*)wr;
            float4 wb = *(const float4*)(wr + 4);
            u64 xp[4] = { xA.x, xA.y, xB.x, xB.y };
            u64 wp[8];
            wp[0] = pack2(wa.x, wa.x); wp[1] = pack2(wa.y, wa.y);
            wp[2] = pack2(wa.z, wa.z); wp[3] = pack2(wa.w, wa.w);
            wp[4] = pack2(wb.x, wb.x); wp[5] = pack2(wb.y, wb.y);
            wp[6] = pack2(wb.z, wb.z); wp[7] = pack2(wb.w, wb.w);
#pragma unroll
            for (int i2 = 0; i2 < 4; ++i2)
#pragma unroll
                for (int m = 0; m < 8; ++m)
                    acc[i2][m] = fma2(xp[i2], wp[m], acc[i2][m]);
        }
        __syncthreads();
    }

    // --- epilogue: add bias, write float4-vectorized
    float gb[8];
#pragma unroll
    for (int m = 0; m < 8; ++m) {
        int g = 8 * ggi + m;
        gb[m] = (g < 60) ? b_ih[g] : 0.f;
    }
#pragma unroll
    for (int i2 = 0; i2 < 4; ++i2) {
        float r0[8], r1[8];
#pragma unroll
        for (int m = 0; m < 8; ++m) {
            unpack2(acc[i2][m], r0[m], r1[m]);
            r0[m] += gb[m]; r1[m] += gb[m];
        }
        size_t row0 = (size_t)b * 512 + t0 + 8 * sgi + 2 * i2;
        float* d0 = g_xw + row0 * 60 + 8 * ggi;
        float* d1 = d0 + 60;
        *(float4*)d0 = make_float4(r0[0], r0[1], r0[2], r0[3]);
        *(float4*)d1 = make_float4(r1[0], r1[1], r1[2], r1[3]);
        if (ggi < 7) {
            *(float4*)(d0 + 4) = make_float4(r0[4], r0[5], r0[6], r0[7]);
            *(float4*)(d1 + 4) = make_float4(r1[4], r1[5], r1[6], r1[7]);
        }
    }
}
#define XW_SMEM_BYTES ((64 * 132 + 64 * 68) * 4)

// ---------------------------------------------------------------------------
// ODE helpers (merged-stage algebra: M = W_f1*W_f5, beta = W_f1*b5)
// ---------------------------------------------------------------------------
struct OdeW {
    float wf1[4], wf2[20], wf3[20], wf4[20], M[20], wf5r[20];
    float b1, b2, b3, b4, b5r, beta;
};

__device__ __forceinline__ float stage_m(const OdeW& W, float hp, float c, float A) {
    float t  = fmaf(c, dot20b(W.M, hp, W.beta), A);
    float h1 = eluf(t);
    float h2 = eluf(dot20b(W.wf2, h1, W.b2));
    float h3 = eluf(dot20b(W.wf3, h2, W.b3));
    return     eluf(dot20b(W.wf4, h3, W.b4));
}

__device__ __forceinline__ float stage_1(const OdeW& W, const float (&z)[4], float& Aout) {
    float A = W.b1;
#pragma unroll
    for (int i = 0; i < 4; ++i) A = fmaf(W.wf1[i], z[i], A);
    Aout = A;
    float h1 = eluf(A);
    float h2 = eluf(dot20b(W.wf2, h1, W.b2));
    float h3 = eluf(dot20b(W.wf3, h2, W.b3));
    return     eluf(dot20b(W.wf4, h3, W.b4));
}

// ---------------------------------------------------------------------------
// Kernel 2: GRU scan (512 steps, cp.async staging, packed f32x2 matvec,
// x-prefetch) + z0 + RK4 ODE, H=1.28 (8 big steps), Hermite dense output.
// ---------------------------------------------------------------------------
__global__ __launch_bounds__(32) void scan_kernel(
    const float* __restrict__ W_hh, const float* __restrict__ b_hh,
    const float* __restrict__ W_rl, const float* __restrict__ b_rl,
    const float* __restrict__ W_f1, const float* __restrict__ b_f1,
    const float* __restrict__ W_f2, const float* __restrict__ b_f2,
    const float* __restrict__ W_f3, const float* __restrict__ b_f3,
    const float* __restrict__ W_f4, const float* __restrict__ b_f4,
    const float* __restrict__ W_f5, const float* __restrict__ b_f5)
{
    __shared__ float xs[2][32 * 60];   // double-buffered 32-step xw chunks

    const int b    = blockIdx.x;
    const int lane = threadIdx.x;
    const int j    = (lane < 20) ? lane : 0;
    const int j4   = (lane < 4)  ? lane : 0;

    // ---- GRU weights, packed in k-pairs ----
    u64 whrp[10], whzp[10], whnp[10], hp[10];
#pragma unroll
    for (int k = 0; k < 10; ++k) {
        whrp[k] = pack2(W_hh[j * 20 + 2 * k],        W_hh[j * 20 + 2 * k + 1]);
        whzp[k] = pack2(W_hh[(20 + j) * 20 + 2 * k], W_hh[(20 + j) * 20 + 2 * k + 1]);
        whnp[k] = pack2(W_hh[(40 + j) * 20 + 2 * k], W_hh[(40 + j) * 20 + 2 * k + 1]);
        hp[k]   = pack2(0.f, 0.f);
    }
    const float bhr = b_hh[j], bhz = b_hh[20 + j], bhn = b_hh[40 + j];
    const u64 zero2 = pack2(0.f, 0.f);
    float hself = 0.f;

    const float* xwb = g_xw + (size_t)b * 512 * 60;

    // issue chunk 0
    {
        const float4* src = (const float4*)xwb;
        unsigned dst = smem_u32(&xs[0][0]);
#pragma unroll
        for (int r = 0; r < 15; ++r) {
            int i = lane + 32 * r;
            CP_ASYNC16(dst + (unsigned)i * 16u, src + i);
        }
        CP_COMMIT();
    }

    for (int c = 0; c < 16; ++c) {
        if (c < 15) {
            const float4* src = (const float4*)(xwb + (size_t)(c + 1) * 1920);
            unsigned dst = smem_u32(&xs[(c + 1) & 1][0]);
#pragma unroll
            for (int r = 0; r < 15; ++r) {
                int i = lane + 32 * r;
                CP_ASYNC16(dst + (unsigned)i * 16u, src + i);
            }
            CP_COMMIT();
            CP_WAIT1();
        } else {
            CP_WAIT0();
        }
        __syncwarp();

        const float* X = &xs[c & 1][0];
        float xr = X[j], xz = X[20 + j], xn = X[40 + j];
        for (int s2 = 0; s2 < 32; ++s2) {
            int sn = (s2 < 31) ? s2 + 1 : s2;
            float nxr = X[sn * 60 + j];
            float nxz = X[sn * 60 + 20 + j];
            float nxn = X[sn * 60 + 40 + j];

            u64 r0 = pack2(bhr, 0.f), r1 = zero2;
            u64 q0 = pack2(bhz, 0.f), q1 = zero2;
            u64 n0 = pack2(bhn, 0.f), n1 = zero2;
#pragma unroll
            for (int kp = 0; kp < 10; kp += 2) {
                r0 = fma2(whrp[kp],     hp[kp],     r0);
                r1 = fma2(whrp[kp + 1], hp[kp + 1], r1);
                q0 = fma2(whzp[kp],     hp[kp],     q0);
                q1 = fma2(whzp[kp + 1], hp[kp + 1], q1);
                n0 = fma2(whnp[kp],     hp[kp],     n0);
                n1 = fma2(whnp[kp + 1], hp[kp + 1], n1);
            }
            float gr = hadd2(add2(r0, r1));
            float gz = hadd2(add2(q0, q1));
            float gn = hadd2(add2(n0, n1));

            float rg   = sigm(xr + gr);
            float zg   = sigm(xz + gz);
            float ng   = tanhfast(xn + rg * gn);
            float hnew = (1.f - zg) * ng + zg * hself;
            hself = hnew;
#pragma unroll
            for (int k = 0; k < 10; ++k) {
                float va = __shfl_sync(FULLMASK, hnew, 2 * k);
                float vb = __shfl_sync(FULLMASK, hnew, 2 * k + 1);
                hp[k] = pack2(va, vb);
            }
            xr = nxr; xz = nxz; xn = nxn;
        }
    }

    // ---- z0 = hT @ W_rl^T + b_rl (packed) ----
    float za;
    {
        u64 s0 = pack2(b_rl[j4], 0.f), s1 = zero2;
#pragma unroll
        for (int k = 0; k < 10; k += 2) {
            s0 = fma2(pack2(W_rl[j4 * 20 + 2 * k],     W_rl[j4 * 20 + 2 * k + 1]), hp[k],     s0);
            s1 = fma2(pack2(W_rl[j4 * 20 + 2 * k + 2], W_rl[j4 * 20 + 2 * k + 3]), hp[k + 1], s1);
        }
        za = hadd2(add2(s0, s1));
    }
    float z[4];
#pragma unroll
    for (int i = 0; i < 4; ++i) z[i] = __shfl_sync(FULLMASK, za, i);

    float4* zb = g_z + (size_t)b * 1024;
    float*  zf = (float*)zb;
    if (lane == 0) zb[0] = make_float4(z[0], z[1], z[2], z[3]);

    // ---- ODE weights ----
    OdeW W;
#pragma unroll
    for (int k = 0; k < 4; ++k) W.wf1[k] = W_f1[j * 4 + k];
#pragma unroll
    for (int k = 0; k < 20; ++k) {
        W.wf2[k]  = W_f2[j * 20 + k];
        W.wf3[k]  = W_f3[j * 20 + k];
        W.wf4[k]  = W_f4[j * 20 + k];
        W.wf5r[k] = W_f5[j4 * 20 + k];
        float m = 0.f;
#pragma unroll
        for (int i = 0; i < 4; ++i) m = fmaf(W.wf1[i], W_f5[i * 20 + k], m);
        W.M[k] = m;
    }
    {
        float bt = 0.f;
#pragma unroll
        for (int i = 0; i < 4; ++i) bt = fmaf(W.wf1[i], b_f5[i], bt);
        W.beta = bt;
    }
    W.b1 = b_f1[j]; W.b2 = b_f2[j]; W.b3 = b_f3[j]; W.b4 = b_f4[j];
    W.b5r = b_f5[j4];

    const float H   = 1.28f;
    const float HD2 = 0.64f;
    const float HD6 = H / 6.0f;
    const int cI = lane & 3;

    float A;
    float h4s1 = stage_1(W, z, A);
    float k1[4];
    {
        float o = dot20b(W.wf5r, h4s1, W.b5r);
#pragma unroll
        for (int i = 0; i < 4; ++i) k1[i] = __shfl_sync(FULLMASK, o, i);
    }

    for (int n = 0; n < 8; ++n) {
        float Hsum = h4s1;
        float h4 = stage_m(W, h4s1, HD2, A);  Hsum = fmaf(2.f, h4, Hsum);
        h4       = stage_m(W, h4,   HD2, A);  Hsum = fmaf(2.f, h4, Hsum);
        h4       = stage_m(W, h4,   H,   A);  Hsum += h4;

        float oS = dot20b(W.wf5r, Hsum, 6.f * W.b5r);
        float zn[4];
#pragma unroll
        for (int i = 0; i < 4; ++i)
            zn[i] = fmaf(HD6, __shfl_sync(FULLMASK, oS, i), z[i]);

        float An;
        float h4n = stage_1(W, zn, An);
        float k1n[4];
        {
            float o1 = dot20b(W.wf5r, h4n, W.b5r);
#pragma unroll
            for (int i = 0; i < 4; ++i) k1n[i] = __shfl_sync(FULLMASK, o1, i);
        }

        float z0c = sel4(z, cI),  z1c = sel4(zn, cI);
        float F0  = H * sel4(k1, cI), F1 = H * sel4(k1n, cI);
#pragma unroll
        for (int r = 0; r < 16; ++r) {
            int vi = lane + 32 * r;
            int p  = vi >> 2;
            int idx = 128 * n + 1 + p;
            if (idx < 1024) {
                float s  = (float)(p + 1) * 0.0078125f;
                float s2 = s * s, om = 1.f - s;
                float h00 = (1.f + 2.f * s) * om * om;
                float h10 = s * om * om;
                float h01 = s2 * (3.f - 2.f * s);
                float h11 = s2 * (s - 1.f);
                zf[idx * 4 + cI] = h00 * z0c + h01 * z1c + h10 * F0 + h11 * F1;
            }
        }

#pragma unroll
        for (int i = 0; i < 4; ++i) { z[i] = zn[i]; k1[i] = k1n[i]; }
        A = An; h4s1 = h4n;
    }
}

// ---------------------------------------------------------------------------
// Kernel 3: decoder. 2 warps per (b, 128-ts tile), 3 gate-rows each.
// ---------------------------------------------------------------------------
__global__ __launch_bounds__(256) void dec_kernel(
    const float* __restrict__ W_d1, const float* __restrict__ b_d1,
    const float* __restrict__ W_d2, const float* __restrict__ b_d2,
    float* __restrict__ out)
{
    const int w    = blockIdx.x * 8 + (threadIdx.x >> 5);   // 0..4095
    const int lane = threadIdx.x & 31;
    const int b    = w >> 4;
    const int rem  = w & 15;
    const int t0   = (rem >> 1) << 7;
    const int half = rem & 1;
    const int j    = (lane < 20) ? lane : 0;

    float wd1[4];
#pragma unroll
    for (int i = 0; i < 4; ++i) wd1[i] = W_d1[j * 4 + i];
    const float bd1v = b_d1[j];

    u64 wd2p[3][10];
    float bd2v[3];
    int gidx[3];
#pragma unroll
    for (int r = 0; r < 3; ++r) {
        int g = lane + 32 * (3 * half + r);
        gidx[r] = g;
#pragma unroll
        for (int k = 0; k < 10; ++k)
            wd2p[r][k] = pack2(W_d2[g * 20 + 2 * k], W_d2[g * 20 + 2 * k + 1]);
        bd2v[r] = b_d2[g];
    }
    const u64 zero2 = pack2(0.f, 0.f);

    const float4* zp = g_z + (size_t)b * 1024 + t0;
    float4 zc = zp[0];
    for (int tt = 0; tt < 128; ++tt) {
        float4 zn = zp[(tt < 127) ? (tt + 1) : tt];
        float t = bd1v;
        t = fmaf(wd1[0], zc.x, t); t = fmaf(wd1[1], zc.y, t);
        t = fmaf(wd1[2], zc.z, t); t = fmaf(wd1[3], zc.w, t);
        float hj = fmaxf(t, 0.f);

        u64 hhp[10];
#pragma unroll
        for (int k = 0; k < 10; ++k) {
            float va = __shfl_sync(FULLMASK, hj, 2 * k);
            float vb = __shfl_sync(FULLMASK, hj, 2 * k + 1);
            hhp[k] = pack2(va, vb);
        }

        const int tg = t0 + tt;
#pragma unroll
        for (int r = 0; r < 3; ++r) {
            u64 s0 = pack2(bd2v[r], 0.f), s1 = zero2;
#pragma unroll
            for (int k = 0; k < 10; k += 2) {
                s0 = fma2(wd2p[r][k],     hhp[k],     s0);
                s1 = fma2(wd2p[r][k + 1], hhp[k + 1], s1);
            }
            float v = hadd2(add2(s0, s1));
            int g = gidx[r];
            int c = g >> 6, f = g & 63;
            out[(((size_t)b * 3 + c) * 1024 + tg) * 64 + f] = v;
        }
        zc = zn;
    }
}

// ---------------------------------------------------------------------------
extern "C" void kernel_launch(void* const* d_in, const int* in_sizes, int n_in,
                              void* d_out, int out_size) {
    const float* x    = (const float*)d_in[0];
    const float* W_ih = (const float*)d_in[2];
    const float* b_ih = (const float*)d_in[3];
    const float* W_hh = (const float*)d_in[4];
    const float* b_hh = (const float*)d_in[5];
    const float* W_rl = (const float*)d_in[6];
    const float* b_rl = (const float*)d_in[7];
    const float* W_f1 = (const float*)d_in[8];
    const float* b_f1 = (const float*)d_in[9];
    const float* W_f2 = (const float*)d_in[10];
    const float* b_f2 = (const float*)d_in[11];
    const float* W_f3 = (const float*)d_in[12];
    const float* b_f3 = (const float*)d_in[13];
    const float* W_f4 = (const float*)d_in[14];
    const float* b_f4 = (const float*)d_in[15];
    const float* W_f5 = (const float*)d_in[16];
    const float* b_f5 = (const float*)d_in[17];
    const float* W_d1 = (const float*)d_in[18];
    const float* b_d1 = (const float*)d_in[19];
    const float* W_d2 = (const float*)d_in[20];
    const float* b_d2 = (const float*)d_in[21];
    float* out = (float*)d_out;

    static bool attr_set = false;
    if (!attr_set) {
        cudaFuncSetAttribute(xw_kernel,
                             cudaFuncAttributeMaxDynamicSharedMemorySize,
                             XW_SMEM_BYTES);
        attr_set = true;
    }

    dim3 g1(4, 256);   // 4 ts-tiles of 128, 256 batch
    xw_kernel<<<g1, 128, XW_SMEM_BYTES>>>(x, W_ih, b_ih);
    scan_kernel<<<256, 32>>>(W_hh, b_hh, W_rl, b_rl,
                             W_f1, b_f1, W_f2, b_f2, W_f3, b_f3,
                             W_f4, b_f4, W_f5, b_f5);
    dec_kernel<<<512, 256>>>(W_d1, b_d1, W_d2, b_d2, out);
}